// round 2
// baseline (speedup 1.0000x reference)
#include <cuda_runtime.h>
#include <mma.h>
#include <math.h>

using namespace nvcuda;

#define B_    2
#define QLEN  1024
#define MLEN  1024
#define KLEN  2048
#define E_    1024
#define H_    16
#define DH_   64
#define HD_   1024
#define FF_   4096

// ---------------- scratch (device globals: allocation-free) ----------------
__device__ float g_cat [(size_t)B_*KLEN*E_];          // 16 MB
__device__ float g_q   [(size_t)B_*QLEN*HD_];         // 8 MB
__device__ float g_qw  [(size_t)B_*QLEN*HD_];
__device__ float g_qr  [(size_t)B_*QLEN*HD_];
__device__ float g_k   [(size_t)B_*KLEN*HD_];         // 16 MB
__device__ float g_v   [(size_t)B_*KLEN*HD_];
__device__ float g_rp  [(size_t)KLEN*HD_];            // 8 MB
__device__ float g_attn[(size_t)B_*H_*QLEN*KLEN];     // 256 MB (AC, then P in-place)
__device__ float g_bd  [(size_t)B_*H_*QLEN*KLEN];     // 256 MB (BD_raw)
__device__ float g_o   [(size_t)B_*QLEN*HD_];
__device__ float g_x   [(size_t)B_*QLEN*E_];
__device__ float g_h1  [(size_t)B_*QLEN*FF_];         // 32 MB
__device__ float g_y   [(size_t)B_*QLEN*E_];

// ---------------- small elementwise kernels ----------------
__global__ void concat_kernel(const float4* __restrict__ member,
                              const float4* __restrict__ w,
                              float4* __restrict__ cat)
{
    int idx = blockIdx.x * 256 + threadIdx.x;        // total (B*KLEN*E)/4 = 1048576
    const int per_b = (KLEN * E_) / 4;               // 524288
    const int half  = (MLEN * E_) / 4;               // 262144
    int b = idx / per_b;
    int r = idx - b * per_b;
    cat[idx] = (r < half) ? member[b * half + r] : w[b * half + (r - half)];
}

__global__ void bias_add_kernel(const float* __restrict__ q,
                                const float* __restrict__ bias,
                                float* __restrict__ out, int n)
{
    int i = blockIdx.x * 256 + threadIdx.x;
    if (i < n) out[i] = q[i] + bias[i & (HD_ - 1)];
}

// ---------------- tf32 WMMA GEMM: C = A @ B (NN), optional relu ----------------
#define BM 128
#define BN 64
#define BK 16
#define ASLD 24
#define BSNN 72
#define BSNT 24

__global__ __launch_bounds__(256) void gemm_nn(
    const float* __restrict__ Ag, const float* __restrict__ Bg, float* __restrict__ Cg,
    int M, int N, int K, int lda, int ldb, int ldc,
    long long sAb, long long sAh, long long sBb, long long sBh,
    long long sCb, long long sCh, int Hn, int relu)
{
    __shared__ float As[BM * ASLD];
    __shared__ float Bs[BK * BSNN];
    int z = blockIdx.z, bb = z / Hn, hh = z - bb * Hn;
    const float* A  = Ag + (long long)bb * sAb + (long long)hh * sAh
                         + (long long)(blockIdx.y * BM) * lda;
    const float* Bp = Bg + (long long)bb * sBb + (long long)hh * sBh + blockIdx.x * BN;
    float*       C  = Cg + (long long)bb * sCb + (long long)hh * sCh
                         + (long long)(blockIdx.y * BM) * ldc + blockIdx.x * BN;

    int tid = threadIdx.x, wid = tid >> 5;
    int wm = wid & 3, wn = wid >> 2;          // 4x2 warp grid, 32x32 per warp

    wmma::fragment<wmma::accumulator, 16, 16, 8, float> c[2][2];
#pragma unroll
    for (int i = 0; i < 2; i++)
#pragma unroll
        for (int j = 0; j < 2; j++) wmma::fill_fragment(c[i][j], 0.f);

    int arow = tid >> 2,  ac4 = (tid & 3)  << 2;   // A: 64 rows x 4 f4, twice
    int brow = tid >> 4,  bc4 = (tid & 15) << 2;   // B: 16 rows x 16 f4

    for (int k0 = 0; k0 < K; k0 += BK) {
        float4 a0 = *(const float4*)(A + (long long)arow * lda + k0 + ac4);
        float4 a1 = *(const float4*)(A + (long long)(arow + 64) * lda + k0 + ac4);
        float4 bv = *(const float4*)(Bp + (long long)(k0 + brow) * ldb + bc4);
        *(float4*)&As[arow * ASLD + ac4]        = a0;
        *(float4*)&As[(arow + 64) * ASLD + ac4] = a1;
        *(float4*)&Bs[brow * BSNN + bc4]        = bv;
        __syncthreads();
#pragma unroll
        for (int kk = 0; kk < BK; kk += 8) {
            wmma::fragment<wmma::matrix_a, 16, 16, 8, wmma::precision::tf32, wmma::row_major> af[2];
            wmma::fragment<wmma::matrix_b, 16, 16, 8, wmma::precision::tf32, wmma::row_major> bf[2];
#pragma unroll
            for (int i = 0; i < 2; i++) {
                wmma::load_matrix_sync(af[i], &As[(wm * 32 + i * 16) * ASLD + kk], ASLD);
#pragma unroll
                for (int t = 0; t < af[i].num_elements; t++)
                    af[i].x[t] = wmma::__float_to_tf32(af[i].x[t]);
            }
#pragma unroll
            for (int j = 0; j < 2; j++) {
                wmma::load_matrix_sync(bf[j], &Bs[kk * BSNN + wn * 32 + j * 16], BSNN);
#pragma unroll
                for (int t = 0; t < bf[j].num_elements; t++)
                    bf[j].x[t] = wmma::__float_to_tf32(bf[j].x[t]);
            }
#pragma unroll
            for (int i = 0; i < 2; i++)
#pragma unroll
                for (int j = 0; j < 2; j++)
                    wmma::mma_sync(c[i][j], af[i], bf[j], c[i][j]);
        }
        __syncthreads();
    }
#pragma unroll
    for (int i = 0; i < 2; i++)
#pragma unroll
        for (int j = 0; j < 2; j++) {
            if (relu) {
#pragma unroll
                for (int t = 0; t < c[i][j].num_elements; t++)
                    c[i][j].x[t] = fmaxf(c[i][j].x[t], 0.f);
            }
            wmma::store_matrix_sync(C + (long long)(wm * 32 + i * 16) * ldc + wn * 32 + j * 16,
                                    c[i][j], ldc, wmma::mem_row_major);
        }
}

// ---------------- tf32 WMMA GEMM: C = A @ B^T (NT, B is [N,K] row-major) ----------------
__global__ __launch_bounds__(256) void gemm_nt(
    const float* __restrict__ Ag, const float* __restrict__ Bg, float* __restrict__ Cg,
    int M, int N, int K, int lda, int ldb, int ldc,
    long long sAb, long long sAh, long long sBb, long long sBh,
    long long sCb, long long sCh, int Hn)
{
    __shared__ float As[BM * ASLD];
    __shared__ float Bs[BN * BSNT];
    int z = blockIdx.z, bb = z / Hn, hh = z - bb * Hn;
    const float* A  = Ag + (long long)bb * sAb + (long long)hh * sAh
                         + (long long)(blockIdx.y * BM) * lda;
    const float* Bp = Bg + (long long)bb * sBb + (long long)hh * sBh
                         + (long long)(blockIdx.x * BN) * ldb;
    float*       C  = Cg + (long long)bb * sCb + (long long)hh * sCh
                         + (long long)(blockIdx.y * BM) * ldc + blockIdx.x * BN;

    int tid = threadIdx.x, wid = tid >> 5;
    int wm = wid & 3, wn = wid >> 2;

    wmma::fragment<wmma::accumulator, 16, 16, 8, float> c[2][2];
#pragma unroll
    for (int i = 0; i < 2; i++)
#pragma unroll
        for (int j = 0; j < 2; j++) wmma::fill_fragment(c[i][j], 0.f);

    int arow = tid >> 2, ac4 = (tid & 3) << 2;   // 64 rows x 4 f4 (twice) for A
    int brow = tid >> 2, bc4 = (tid & 3) << 2;   // 64 rows x 4 f4 for B

    for (int k0 = 0; k0 < K; k0 += BK) {
        float4 a0 = *(const float4*)(A + (long long)arow * lda + k0 + ac4);
        float4 a1 = *(const float4*)(A + (long long)(arow + 64) * lda + k0 + ac4);
        float4 bv = *(const float4*)(Bp + (long long)brow * ldb + k0 + bc4);
        *(float4*)&As[arow * ASLD + ac4]        = a0;
        *(float4*)&As[(arow + 64) * ASLD + ac4] = a1;
        *(float4*)&Bs[brow * BSNT + bc4]        = bv;
        __syncthreads();
#pragma unroll
        for (int kk = 0; kk < BK; kk += 8) {
            wmma::fragment<wmma::matrix_a, 16, 16, 8, wmma::precision::tf32, wmma::row_major> af[2];
            wmma::fragment<wmma::matrix_b, 16, 16, 8, wmma::precision::tf32, wmma::col_major> bf[2];
#pragma unroll
            for (int i = 0; i < 2; i++) {
                wmma::load_matrix_sync(af[i], &As[(wm * 32 + i * 16) * ASLD + kk], ASLD);
#pragma unroll
                for (int t = 0; t < af[i].num_elements; t++)
                    af[i].x[t] = wmma::__float_to_tf32(af[i].x[t]);
            }
#pragma unroll
            for (int j = 0; j < 2; j++) {
                wmma::load_matrix_sync(bf[j], &Bs[(wn * 32 + j * 16) * BSNT + kk], BSNT);
#pragma unroll
                for (int t = 0; t < bf[j].num_elements; t++)
                    bf[j].x[t] = wmma::__float_to_tf32(bf[j].x[t]);
            }
#pragma unroll
            for (int i = 0; i < 2; i++)
#pragma unroll
                for (int j = 0; j < 2; j++)
                    wmma::mma_sync(c[i][j], af[i], bf[j], c[i][j]);
        }
        __syncthreads();
    }
#pragma unroll
    for (int i = 0; i < 2; i++)
#pragma unroll
        for (int j = 0; j < 2; j++)
            wmma::store_matrix_sync(C + (long long)(wm * 32 + i * 16) * ldc + wn * 32 + j * 16,
                                    c[i][j], ldc, wmma::mem_row_major);
}

// ---------------- shift + mask + softmax (in-place on g_attn) ----------------
// logits[i,j] = (AC[i,j] + BD_raw[i, j + QLEN-1-i]) / 32 for j <= i+MLEN, else masked.
__global__ __launch_bounds__(256) void softmax_kernel()
{
    int i = blockIdx.x, bh = blockIdx.y, tid = threadIdx.x;
    size_t base = ((size_t)bh * QLEN + i) * KLEN;
    const float* ac = g_attn + base;
    const float* bd = g_bd + base;
    float* p = g_attn + base;
    int vlen = i + MLEN + 1;               // valid keys: j in [0, i+MLEN]
    int off  = QLEN - 1 - i;               // rel_shift gather offset
    const float scale = 0.03125f;          // 1/sqrt(1024)

    __shared__ float red[256];
    float mx = -1e30f;
    for (int j = tid; j < vlen; j += 256)
        mx = fmaxf(mx, (ac[j] + bd[j + off]) * scale);
    red[tid] = mx; __syncthreads();
    for (int s = 128; s; s >>= 1) { if (tid < s) red[tid] = fmaxf(red[tid], red[tid + s]); __syncthreads(); }
    float m = red[0]; __syncthreads();

    float sum = 0.f;
    for (int j = tid; j < vlen; j += 256) {
        float e = expf((ac[j] + bd[j + off]) * scale - m);
        p[j] = e;
        sum += e;
    }
    red[tid] = sum; __syncthreads();
    for (int s = 128; s; s >>= 1) { if (tid < s) red[tid] += red[tid + s]; __syncthreads(); }
    float inv = 1.f / red[0];

    for (int j = tid; j < KLEN; j += 256)
        p[j] = (j < vlen) ? p[j] * inv : 0.f;
}

// ---------------- fused add + LayerNorm ----------------
__global__ __launch_bounds__(256) void add_ln_kernel(
    const float* __restrict__ a, const float* __restrict__ b,
    const float* __restrict__ gamma, const float* __restrict__ beta,
    float* __restrict__ out)
{
    int row = blockIdx.x, tid = threadIdx.x;
    __shared__ float sh[E_];
    __shared__ float red[256];
    size_t base = (size_t)row * E_;

    float s = 0.f;
    for (int c = tid; c < E_; c += 256) { float v = a[base + c] + b[base + c]; sh[c] = v; s += v; }
    red[tid] = s; __syncthreads();
    for (int st = 128; st; st >>= 1) { if (tid < st) red[tid] += red[tid + st]; __syncthreads(); }
    float mu = red[0] * (1.f / E_); __syncthreads();

    float vs = 0.f;
    for (int c = tid; c < E_; c += 256) { float d = sh[c] - mu; vs += d * d; }
    red[tid] = vs; __syncthreads();
    for (int st = 128; st; st >>= 1) { if (tid < st) red[tid] += red[tid + st]; __syncthreads(); }
    float rstd = rsqrtf(red[0] * (1.f / E_) + 1e-3f);

    for (int c = tid; c < E_; c += 256)
        out[base + c] = (sh[c] - mu) * rstd * gamma[c] + beta[c];
}

// ---------------- host ----------------
extern "C" void kernel_launch(void* const* d_in, const int* in_sizes, int n_in,
                              void* d_out, int out_size)
{
    const float* w      = (const float*)d_in[0];
    const float* r      = (const float*)d_in[1];
    const float* member = (const float*)d_in[2];
    // d_in[3] = attn_mask (unused; mask is analytic)
    const float* Wq  = (const float*)d_in[4];
    const float* Wk  = (const float*)d_in[5];
    const float* Wv  = (const float*)d_in[6];
    const float* Wr  = (const float*)d_in[7];
    const float* Wo  = (const float*)d_in[8];
    const float* rwb = (const float*)d_in[9];
    const float* rrb = (const float*)d_in[10];
    const float* ln1g = (const float*)d_in[11];
    const float* ln1b = (const float*)d_in[12];
    const float* W1  = (const float*)d_in[13];
    const float* W2  = (const float*)d_in[14];
    const float* ln2g = (const float*)d_in[15];
    const float* ln2b = (const float*)d_in[16];

    float *cat_, *q_, *qw_, *qr_, *k_, *v_, *rp_, *attn_, *bd_, *o_, *x_, *h1_, *y_;
    cudaGetSymbolAddress((void**)&cat_,  g_cat);
    cudaGetSymbolAddress((void**)&q_,    g_q);
    cudaGetSymbolAddress((void**)&qw_,   g_qw);
    cudaGetSymbolAddress((void**)&qr_,   g_qr);
    cudaGetSymbolAddress((void**)&k_,    g_k);
    cudaGetSymbolAddress((void**)&v_,    g_v);
    cudaGetSymbolAddress((void**)&rp_,   g_rp);
    cudaGetSymbolAddress((void**)&attn_, g_attn);
    cudaGetSymbolAddress((void**)&bd_,   g_bd);
    cudaGetSymbolAddress((void**)&o_,    g_o);
    cudaGetSymbolAddress((void**)&x_,    g_x);
    cudaGetSymbolAddress((void**)&h1_,   g_h1);
    cudaGetSymbolAddress((void**)&y_,    g_y);

    // 1) cat = concat(member, w)
    concat_kernel<<<4096, 256>>>((const float4*)member, (const float4*)w, (float4*)cat_);

    // 2) projections (tf32)
    gemm_nn<<<dim3(16, 16, 1), 256>>>(w,    Wq, q_,  2048, 1024, 1024, 1024, 1024, 1024, 0,0,0,0,0,0, 1, 0);
    gemm_nn<<<dim3(16, 32, 1), 256>>>(cat_, Wk, k_,  4096, 1024, 1024, 1024, 1024, 1024, 0,0,0,0,0,0, 1, 0);
    gemm_nn<<<dim3(16, 32, 1), 256>>>(cat_, Wv, v_,  4096, 1024, 1024, 1024, 1024, 1024, 0,0,0,0,0,0, 1, 0);
    gemm_nn<<<dim3(16, 16, 1), 256>>>(r,    Wr, rp_, 2048, 1024, 1024, 1024, 1024, 1024, 0,0,0,0,0,0, 1, 0);

    // 3) q + r_w_bias / q + r_r_bias
    bias_add_kernel<<<8192, 256>>>(q_, rwb, qw_, 2097152);
    bias_add_kernel<<<8192, 256>>>(q_, rrb, qr_, 2097152);

    // 4) AC[b,h] = qw[b,:,h,:] @ k[b,:,h,:]^T     (batched over 32 bh)
    gemm_nt<<<dim3(32, 8, 32), 256>>>(qw_, k_, attn_,
        1024, 2048, 64, 1024, 1024, 2048,
        1048576LL, 64LL, 2097152LL, 64LL, 33554432LL, 2097152LL, 16);

    // 5) BD_raw[b,h] = qr[b,:,h,:] @ rp[:,h,:]^T  (B shared over batch)
    gemm_nt<<<dim3(32, 8, 32), 256>>>(qr_, rp_, bd_,
        1024, 2048, 64, 1024, 1024, 2048,
        1048576LL, 64LL, 0LL, 64LL, 33554432LL, 2097152LL, 16);

    // 6) rel_shift + mask + softmax (in-place: g_attn := P)
    softmax_kernel<<<dim3(QLEN, B_ * H_), 256>>>();

    // 7) O[b,:,h,:] = P[b,h] @ v[b,:,h,:]
    gemm_nn<<<dim3(1, 8, 32), 256>>>(attn_, v_, o_,
        1024, 64, 2048, 2048, 1024, 1024,
        33554432LL, 2097152LL, 2097152LL, 64LL, 1048576LL, 64LL, 16, 0);

    // 8) o @ Wo
    gemm_nn<<<dim3(16, 16, 1), 256>>>(o_, Wo, y_, 2048, 1024, 1024, 1024, 1024, 1024, 0,0,0,0,0,0, 1, 0);

    // 9) x = LN(w + o@Wo)
    add_ln_kernel<<<2048, 256>>>(w, y_, ln1g, ln1b, x_);

    // 10) h1 = relu(x @ W1)
    gemm_nn<<<dim3(64, 16, 1), 256>>>(x_, W1, h1_, 2048, 4096, 1024, 1024, 4096, 4096, 0,0,0,0,0,0, 1, 1);

    // 11) y = h1 @ W2
    gemm_nn<<<dim3(16, 16, 1), 256>>>(h1_, W2, y_, 2048, 1024, 4096, 4096, 1024, 1024, 0,0,0,0,0,0, 1, 0);

    // 12) out = LN(y + x)
    add_ln_kernel<<<2048, 256>>>(y_, x_, ln2g, ln2b, (float*)d_out);
}

// round 3
// speedup vs baseline: 1.7194x; 1.7194x over previous
#include <cuda_runtime.h>
#include <mma.h>
#include <math.h>

using namespace nvcuda;

#define B_    2
#define QLEN  1024
#define MLEN  1024
#define KLEN  2048
#define E_    1024
#define H_    16
#define DH_   64
#define HD_   1024
#define FF_   4096

// ---------------- scratch (device globals: allocation-free) ----------------
__device__ float g_cat [(size_t)B_*KLEN*E_];
__device__ float g_q   [(size_t)B_*QLEN*HD_];
__device__ float g_qw  [(size_t)B_*QLEN*HD_];
__device__ float g_qr  [(size_t)B_*QLEN*HD_];
__device__ float g_k   [(size_t)B_*KLEN*HD_];
__device__ float g_v   [(size_t)B_*KLEN*HD_];
__device__ float g_rp  [(size_t)KLEN*HD_];
__device__ float g_attn[(size_t)B_*H_*QLEN*KLEN];     // AC, then P in-place
__device__ float g_bd  [(size_t)B_*H_*QLEN*KLEN];     // BD_raw
__device__ float g_o   [(size_t)B_*QLEN*HD_];
__device__ float g_x   [(size_t)B_*QLEN*E_];
__device__ float g_h1  [(size_t)B_*QLEN*FF_];
__device__ float g_y   [(size_t)B_*QLEN*E_];

// ---------------- helpers ----------------
__device__ __forceinline__ void cpa16(float* dst, const float* src) {
    unsigned d = (unsigned)__cvta_generic_to_shared(dst);
    asm volatile("cp.async.cg.shared.global [%0], [%1], 16;\n" :: "r"(d), "l"(src));
}
__device__ __forceinline__ void cpa_commit() { asm volatile("cp.async.commit_group;\n"); }

// ---------------- small elementwise kernels ----------------
__global__ void concat_kernel(const float4* __restrict__ member,
                              const float4* __restrict__ w,
                              float4* __restrict__ cat)
{
    int idx = blockIdx.x * 256 + threadIdx.x;
    const int per_b = (KLEN * E_) / 4;
    const int half  = (MLEN * E_) / 4;
    int b = idx / per_b;
    int r = idx - b * per_b;
    cat[idx] = (r < half) ? member[b * half + r] : w[b * half + (r - half)];
}

__global__ void bias_add_kernel(const float* __restrict__ q,
                                const float* __restrict__ bias,
                                float* __restrict__ out, int n)
{
    int i = blockIdx.x * 256 + threadIdx.x;
    if (i < n) out[i] = q[i] + bias[i & (HD_ - 1)];
}

// ---------------- double-buffered cp.async tf32 WMMA GEMM ----------------
// NT=0: C = A @ B (B row-major [K,N]); NT=1: C = A @ B^T (B row-major [N,K])
template<int BM, int BN, int BK, int WM, int WN, int NT, int RELU>
__global__ void __launch_bounds__(256) gemm_db(
    const float* __restrict__ Ag, const float* __restrict__ Bg, float* __restrict__ Cg,
    int M, int N, int K, int lda, int ldb, int ldc,
    long long sAb, long long sAh, long long sBb, long long sBh,
    long long sCb, long long sCh, int Hn)
{
    constexpr int AL   = BK + 4;            // padded lead for A (and NT B)
    constexpr int BLnn = BN + 4;            // padded lead for NN B
    constexpr int ASZ  = BM * AL;
    constexpr int BSZ  = NT ? BN * AL : BK * BLnn;
    constexpr int STG  = ASZ + BSZ;
    constexpr int FM   = WM / 16;
    constexpr int FN   = WN / 16;
    constexpr int WROWS = BM / WM;

    extern __shared__ float sm[];

    int z = blockIdx.z, bb = z / Hn, hh = z - bb * Hn;
    const float* A  = Ag + (long long)bb * sAb + (long long)hh * sAh
                         + (long long)(blockIdx.y * BM) * lda;
    const float* Bp = Bg + (long long)bb * sBb + (long long)hh * sBh
                         + (NT ? (long long)(blockIdx.x * BN) * ldb
                               : (long long)(blockIdx.x * BN));
    float*       C  = Cg + (long long)bb * sCb + (long long)hh * sCh
                         + (long long)(blockIdx.y * BM) * ldc + blockIdx.x * BN;

    int tid = threadIdx.x;
    int wid = tid >> 5;
    int wm = wid % WROWS, wn = wid / WROWS;

    wmma::fragment<wmma::accumulator, 16, 16, 8, float> acc[FM][FN];
#pragma unroll
    for (int i = 0; i < FM; i++)
#pragma unroll
        for (int j = 0; j < FN; j++) wmma::fill_fragment(acc[i][j], 0.f);

    auto load_tile = [&](int s, int k0) {
        float* Ab = sm + s * STG;
        float* Bb = Ab + ASZ;
#pragma unroll
        for (int c = tid; c < BM * BK / 4; c += 256) {
            int row = c / (BK / 4), c4 = c % (BK / 4);
            cpa16(&Ab[row * AL + c4 * 4], A + (long long)row * lda + k0 + c4 * 4);
        }
        if (NT) {
#pragma unroll
            for (int c = tid; c < BN * BK / 4; c += 256) {
                int row = c / (BK / 4), c4 = c % (BK / 4);
                cpa16(&Bb[row * AL + c4 * 4], Bp + (long long)row * ldb + k0 + c4 * 4);
            }
        } else {
#pragma unroll
            for (int c = tid; c < BK * BN / 4; c += 256) {
                int row = c / (BN / 4), c4 = c % (BN / 4);
                cpa16(&Bb[row * BLnn + c4 * 4], Bp + (long long)(k0 + row) * ldb + c4 * 4);
            }
        }
        cpa_commit();
    };

    int niter = K / BK;
    load_tile(0, 0);

    for (int it = 0; it < niter; ++it) {
        if (it + 1 < niter) {
            load_tile((it + 1) & 1, (it + 1) * BK);
            asm volatile("cp.async.wait_group 1;\n");
        } else {
            asm volatile("cp.async.wait_group 0;\n");
        }
        __syncthreads();

        float* Acur = sm + (it & 1) * STG;
        float* Bcur = Acur + ASZ;

#pragma unroll
        for (int kk = 0; kk < BK; kk += 8) {
            wmma::fragment<wmma::matrix_a, 16, 16, 8, wmma::precision::tf32, wmma::row_major> af[FM];
#pragma unroll
            for (int i = 0; i < FM; i++) {
                wmma::load_matrix_sync(af[i], &Acur[(wm * WM + i * 16) * AL + kk], AL);
#pragma unroll
                for (int t = 0; t < af[i].num_elements; t++)
                    af[i].x[t] = wmma::__float_to_tf32(af[i].x[t]);
            }
            if (NT) {
                wmma::fragment<wmma::matrix_b, 16, 16, 8, wmma::precision::tf32, wmma::col_major> bf[FN];
#pragma unroll
                for (int j = 0; j < FN; j++) {
                    wmma::load_matrix_sync(bf[j], &Bcur[(wn * WN + j * 16) * AL + kk], AL);
#pragma unroll
                    for (int t = 0; t < bf[j].num_elements; t++)
                        bf[j].x[t] = wmma::__float_to_tf32(bf[j].x[t]);
                }
#pragma unroll
                for (int i = 0; i < FM; i++)
#pragma unroll
                    for (int j = 0; j < FN; j++)
                        wmma::mma_sync(acc[i][j], af[i], bf[j], acc[i][j]);
            } else {
                wmma::fragment<wmma::matrix_b, 16, 16, 8, wmma::precision::tf32, wmma::row_major> bf[FN];
#pragma unroll
                for (int j = 0; j < FN; j++) {
                    wmma::load_matrix_sync(bf[j], &Bcur[kk * BLnn + wn * WN + j * 16], BLnn);
#pragma unroll
                    for (int t = 0; t < bf[j].num_elements; t++)
                        bf[j].x[t] = wmma::__float_to_tf32(bf[j].x[t]);
                }
#pragma unroll
                for (int i = 0; i < FM; i++)
#pragma unroll
                    for (int j = 0; j < FN; j++)
                        wmma::mma_sync(acc[i][j], af[i], bf[j], acc[i][j]);
            }
        }
        __syncthreads();
    }

#pragma unroll
    for (int i = 0; i < FM; i++)
#pragma unroll
        for (int j = 0; j < FN; j++) {
            if (RELU) {
#pragma unroll
                for (int t = 0; t < acc[i][j].num_elements; t++)
                    acc[i][j].x[t] = fmaxf(acc[i][j].x[t], 0.f);
            }
            wmma::store_matrix_sync(C + (long long)(wm * WM + i * 16) * ldc + wn * WN + j * 16,
                                    acc[i][j], ldc, wmma::mem_row_major);
        }
}

// ---------------- shift + mask + softmax (in-place on g_attn) ----------------
__global__ void __launch_bounds__(256) softmax_kernel()
{
    int i = blockIdx.x, bh = blockIdx.y, tid = threadIdx.x;
    size_t base = ((size_t)bh * QLEN + i) * KLEN;
    const float* ac = g_attn + base;
    const float* bd = g_bd + base;
    float* p = g_attn + base;
    int vlen = i + MLEN + 1;
    int off  = QLEN - 1 - i;
    const float scale = 0.03125f;

    __shared__ float red[256];
    float mx = -1e30f;
    for (int j = tid; j < vlen; j += 256)
        mx = fmaxf(mx, (ac[j] + bd[j + off]) * scale);
    red[tid] = mx; __syncthreads();
    for (int s = 128; s; s >>= 1) { if (tid < s) red[tid] = fmaxf(red[tid], red[tid + s]); __syncthreads(); }
    float m = red[0]; __syncthreads();

    float sum = 0.f;
    for (int j = tid; j < vlen; j += 256) {
        float e = expf((ac[j] + bd[j + off]) * scale - m);
        p[j] = e;
        sum += e;
    }
    red[tid] = sum; __syncthreads();
    for (int s = 128; s; s >>= 1) { if (tid < s) red[tid] += red[tid + s]; __syncthreads(); }
    float inv = 1.f / red[0];

    for (int j = tid; j < KLEN; j += 256)
        p[j] = (j < vlen) ? p[j] * inv : 0.f;
}

// ---------------- fused add + LayerNorm ----------------
__global__ void __launch_bounds__(256) add_ln_kernel(
    const float* __restrict__ a, const float* __restrict__ b,
    const float* __restrict__ gamma, const float* __restrict__ beta,
    float* __restrict__ out)
{
    int row = blockIdx.x, tid = threadIdx.x;
    __shared__ float sh[E_];
    __shared__ float red[256];
    size_t base = (size_t)row * E_;

    float s = 0.f;
    for (int c = tid; c < E_; c += 256) { float v = a[base + c] + b[base + c]; sh[c] = v; s += v; }
    red[tid] = s; __syncthreads();
    for (int st = 128; st; st >>= 1) { if (tid < st) red[tid] += red[tid + st]; __syncthreads(); }
    float mu = red[0] * (1.f / E_); __syncthreads();

    float vs = 0.f;
    for (int c = tid; c < E_; c += 256) { float d = sh[c] - mu; vs += d * d; }
    red[tid] = vs; __syncthreads();
    for (int st = 128; st; st >>= 1) { if (tid < st) red[tid] += red[tid + st]; __syncthreads(); }
    float rstd = rsqrtf(red[0] * (1.f / E_) + 1e-3f);

    for (int c = tid; c < E_; c += 256)
        out[base + c] = (sh[c] - mu) * rstd * gamma[c] + beta[c];
}

// ---------------- host ----------------
// kernel instantiations
#define GEMM_NN  gemm_db<128,128,32,64,32,0,0>
#define GEMM_NN_RELU gemm_db<128,128,32,64,32,0,1>
#define GEMM_NT  gemm_db<128,128,32,64,32,1,0>
#define GEMM_PV  gemm_db<128, 64,32,32,32,0,0>

static const int SZ_NN = 2 * (128*36 + 32*132) * 4;   // 70656
static const int SZ_NT = 2 * (128*36 + 128*36) * 4;   // 73728
static const int SZ_PV = 2 * (128*36 + 32*68) * 4;    // 54272

extern "C" void kernel_launch(void* const* d_in, const int* in_sizes, int n_in,
                              void* d_out, int out_size)
{
    const float* w      = (const float*)d_in[0];
    const float* r      = (const float*)d_in[1];
    const float* member = (const float*)d_in[2];
    const float* Wq  = (const float*)d_in[4];
    const float* Wk  = (const float*)d_in[5];
    const float* Wv  = (const float*)d_in[6];
    const float* Wr  = (const float*)d_in[7];
    const float* Wo  = (const float*)d_in[8];
    const float* rwb = (const float*)d_in[9];
    const float* rrb = (const float*)d_in[10];
    const float* ln1g = (const float*)d_in[11];
    const float* ln1b = (const float*)d_in[12];
    const float* W1  = (const float*)d_in[13];
    const float* W2  = (const float*)d_in[14];
    const float* ln2g = (const float*)d_in[15];
    const float* ln2b = (const float*)d_in[16];

    float *cat_, *q_, *qw_, *qr_, *k_, *v_, *rp_, *attn_, *bd_, *o_, *x_, *h1_, *y_;
    cudaGetSymbolAddress((void**)&cat_,  g_cat);
    cudaGetSymbolAddress((void**)&q_,    g_q);
    cudaGetSymbolAddress((void**)&qw_,   g_qw);
    cudaGetSymbolAddress((void**)&qr_,   g_qr);
    cudaGetSymbolAddress((void**)&k_,    g_k);
    cudaGetSymbolAddress((void**)&v_,    g_v);
    cudaGetSymbolAddress((void**)&rp_,   g_rp);
    cudaGetSymbolAddress((void**)&attn_, g_attn);
    cudaGetSymbolAddress((void**)&bd_,   g_bd);
    cudaGetSymbolAddress((void**)&o_,    g_o);
    cudaGetSymbolAddress((void**)&x_,    g_x);
    cudaGetSymbolAddress((void**)&h1_,   g_h1);
    cudaGetSymbolAddress((void**)&y_,    g_y);

    cudaFuncSetAttribute(GEMM_NN,      cudaFuncAttributeMaxDynamicSharedMemorySize, SZ_NN);
    cudaFuncSetAttribute(GEMM_NN_RELU, cudaFuncAttributeMaxDynamicSharedMemorySize, SZ_NN);
    cudaFuncSetAttribute(GEMM_NT,      cudaFuncAttributeMaxDynamicSharedMemorySize, SZ_NT);
    cudaFuncSetAttribute(GEMM_PV,      cudaFuncAttributeMaxDynamicSharedMemorySize, SZ_PV);

    // 1) cat = concat(member, w)
    concat_kernel<<<4096, 256>>>((const float4*)member, (const float4*)w, (float4*)cat_);

    // 2) projections
    GEMM_NN<<<dim3(8, 16, 1), 256, SZ_NN>>>(w,    Wq, q_,  2048, 1024, 1024, 1024, 1024, 1024, 0,0,0,0,0,0, 1);
    GEMM_NN<<<dim3(8, 32, 1), 256, SZ_NN>>>(cat_, Wk, k_,  4096, 1024, 1024, 1024, 1024, 1024, 0,0,0,0,0,0, 1);
    GEMM_NN<<<dim3(8, 32, 1), 256, SZ_NN>>>(cat_, Wv, v_,  4096, 1024, 1024, 1024, 1024, 1024, 0,0,0,0,0,0, 1);
    GEMM_NN<<<dim3(8, 16, 1), 256, SZ_NN>>>(r,    Wr, rp_, 2048, 1024, 1024, 1024, 1024, 1024, 0,0,0,0,0,0, 1);

    // 3) biased q copies
    bias_add_kernel<<<8192, 256>>>(q_, rwb, qw_, 2097152);
    bias_add_kernel<<<8192, 256>>>(q_, rrb, qr_, 2097152);

    // 4) AC[b,h] = qw @ k^T   (batched over 32 bh)
    GEMM_NT<<<dim3(16, 8, 32), 256, SZ_NT>>>(qw_, k_, attn_,
        1024, 2048, 64, 1024, 1024, 2048,
        1048576LL, 64LL, 2097152LL, 64LL, 33554432LL, 2097152LL, 16);

    // 5) BD_raw[b,h] = qr @ rp^T  (rp shared over batch)
    GEMM_NT<<<dim3(16, 8, 32), 256, SZ_NT>>>(qr_, rp_, bd_,
        1024, 2048, 64, 1024, 1024, 2048,
        1048576LL, 64LL, 0LL, 64LL, 33554432LL, 2097152LL, 16);

    // 6) rel_shift + mask + softmax (in-place)
    softmax_kernel<<<dim3(QLEN, B_ * H_), 256>>>();

    // 7) O = P @ v
    GEMM_PV<<<dim3(1, 8, 32), 256, SZ_PV>>>(attn_, v_, o_,
        1024, 64, 2048, 2048, 1024, 1024,
        33554432LL, 2097152LL, 2097152LL, 64LL, 1048576LL, 64LL, 16);

    // 8) o @ Wo
    GEMM_NN<<<dim3(8, 16, 1), 256, SZ_NN>>>(o_, Wo, y_, 2048, 1024, 1024, 1024, 1024, 1024, 0,0,0,0,0,0, 1);

    // 9) x = LN(w + o@Wo)
    add_ln_kernel<<<2048, 256>>>(w, y_, ln1g, ln1b, x_);

    // 10) h1 = relu(x @ W1)
    GEMM_NN_RELU<<<dim3(32, 16, 1), 256, SZ_NN>>>(x_, W1, h1_, 2048, 4096, 1024, 1024, 4096, 4096, 0,0,0,0,0,0, 1);

    // 11) y = h1 @ W2
    GEMM_NN<<<dim3(8, 16, 1), 256, SZ_NN>>>(h1_, W2, y_, 2048, 1024, 4096, 4096, 1024, 1024, 0,0,0,0,0,0, 1);

    // 12) out = LN(y + x)
    add_ln_kernel<<<2048, 256>>>(y_, x_, ln2g, ln2b, (float*)d_out);
}

// round 4
// speedup vs baseline: 1.8339x; 1.0666x over previous
#include <cuda_runtime.h>
#include <mma.h>
#include <math.h>

using namespace nvcuda;

#define B_    2
#define QLEN  1024
#define MLEN  1024
#define KLEN  2048
#define E_    1024
#define H_    16
#define DH_   64
#define HD_   1024
#define FF_   4096

// ---------------- scratch (device globals: allocation-free) ----------------
__device__ float g_cat [(size_t)B_*KLEN*E_];
__device__ float g_q   [(size_t)B_*QLEN*HD_];
__device__ float g_qw  [(size_t)B_*QLEN*HD_];
__device__ float g_qr  [(size_t)B_*QLEN*HD_];
__device__ float g_k   [(size_t)B_*KLEN*HD_];
__device__ float g_v   [(size_t)B_*KLEN*HD_];
__device__ float g_rp  [(size_t)KLEN*HD_];
__device__ float g_attn[(size_t)B_*H_*QLEN*KLEN];     // AC, then P in-place
__device__ float g_bd  [(size_t)B_*H_*QLEN*KLEN];     // BD_raw
__device__ float g_o   [(size_t)B_*QLEN*HD_];
__device__ float g_x   [(size_t)B_*QLEN*E_];
__device__ float g_h1  [(size_t)B_*QLEN*FF_];
__device__ float g_y   [(size_t)B_*QLEN*E_];

// ---------------- helpers ----------------
__device__ __forceinline__ void cpa16(float* dst, const float* src) {
    unsigned d = (unsigned)__cvta_generic_to_shared(dst);
    asm volatile("cp.async.cg.shared.global [%0], [%1], 16;\n" :: "r"(d), "l"(src));
}
__device__ __forceinline__ void cpa_commit() { asm volatile("cp.async.commit_group;\n"); }

// ---------------- small elementwise kernels ----------------
__global__ void concat_kernel(const float4* __restrict__ member,
                              const float4* __restrict__ w,
                              float4* __restrict__ cat)
{
    int idx = blockIdx.x * 256 + threadIdx.x;
    const int per_b = (KLEN * E_) / 4;
    const int half  = (MLEN * E_) / 4;
    int b = idx / per_b;
    int r = idx - b * per_b;
    cat[idx] = (r < half) ? member[b * half + r] : w[b * half + (r - half)];
}

__global__ void bias_add2_kernel(const float* __restrict__ q,
                                 const float* __restrict__ b1,
                                 const float* __restrict__ b2,
                                 float* __restrict__ o1,
                                 float* __restrict__ o2, int n)
{
    int i = blockIdx.x * 256 + threadIdx.x;
    if (i < n) {
        float v = q[i];
        int c = i & (HD_ - 1);
        o1[i] = v + b1[c];
        o2[i] = v + b2[c];
    }
}

// ---------------- 3-stage cp.async tf32 WMMA GEMM ----------------
// NT=0: C = A @ B (B row-major [K,N]); NT=1: C = A @ B^T (B row-major [N,K])
template<int BM, int BN, int BK, int WM, int WN, int NT, int RELU>
__global__ void __launch_bounds__(256, 2) gemm_db(
    const float* __restrict__ Ag, const float* __restrict__ Bg, float* __restrict__ Cg,
    int M, int N, int K, int lda, int ldb, int ldc,
    long long sAb, long long sAh, long long sBb, long long sBh,
    long long sCb, long long sCh, int Hn)
{
    constexpr int AL   = BK + 4;            // padded lead for A (and NT B)
    constexpr int BLnn = BN + 4;            // padded lead for NN B
    constexpr int ASZ  = BM * AL;
    constexpr int BSZ  = NT ? BN * AL : BK * BLnn;
    constexpr int STG  = ASZ + BSZ;
    constexpr int NSTG = 3;
    constexpr int FM   = WM / 16;
    constexpr int FN   = WN / 16;
    constexpr int WROWS = BM / WM;

    extern __shared__ float sm[];

    int z = blockIdx.z, bb = z / Hn, hh = z - bb * Hn;
    const float* A  = Ag + (long long)bb * sAb + (long long)hh * sAh
                         + (long long)(blockIdx.y * BM) * lda;
    const float* Bp = Bg + (long long)bb * sBb + (long long)hh * sBh
                         + (NT ? (long long)(blockIdx.x * BN) * ldb
                               : (long long)(blockIdx.x * BN));
    float*       C  = Cg + (long long)bb * sCb + (long long)hh * sCh
                         + (long long)(blockIdx.y * BM) * ldc + blockIdx.x * BN;

    int tid = threadIdx.x;
    int wid = tid >> 5;
    int wm = wid % WROWS, wn = wid / WROWS;

    wmma::fragment<wmma::accumulator, 16, 16, 8, float> acc[FM][FN];
#pragma unroll
    for (int i = 0; i < FM; i++)
#pragma unroll
        for (int j = 0; j < FN; j++) wmma::fill_fragment(acc[i][j], 0.f);

    auto load_tile = [&](int s, int k0) {
        float* Ab = sm + s * STG;
        float* Bb = Ab + ASZ;
#pragma unroll
        for (int c = tid; c < BM * BK / 4; c += 256) {
            int row = c / (BK / 4), c4 = c % (BK / 4);
            cpa16(&Ab[row * AL + c4 * 4], A + (long long)row * lda + k0 + c4 * 4);
        }
        if (NT) {
#pragma unroll
            for (int c = tid; c < BN * BK / 4; c += 256) {
                int row = c / (BK / 4), c4 = c % (BK / 4);
                cpa16(&Bb[row * AL + c4 * 4], Bp + (long long)row * ldb + k0 + c4 * 4);
            }
        } else {
#pragma unroll
            for (int c = tid; c < BK * BN / 4; c += 256) {
                int row = c / (BN / 4), c4 = c % (BN / 4);
                cpa16(&Bb[row * BLnn + c4 * 4], Bp + (long long)(k0 + row) * ldb + c4 * 4);
            }
        }
        cpa_commit();
    };

    int niter = K / BK;
    load_tile(0, 0);
    if (niter > 1) load_tile(1, BK);

    for (int it = 0; it < niter; ++it) {
        asm volatile("cp.async.wait_group 1;\n");
        __syncthreads();
        if (it + 2 < niter) load_tile((it + 2) % NSTG, (it + 2) * BK);

        float* Acur = sm + (it % NSTG) * STG;
        float* Bcur = Acur + ASZ;

#pragma unroll
        for (int kk = 0; kk < BK; kk += 8) {
            wmma::fragment<wmma::matrix_a, 16, 16, 8, wmma::precision::tf32, wmma::row_major> af[FM];
#pragma unroll
            for (int i = 0; i < FM; i++)
                wmma::load_matrix_sync(af[i], &Acur[(wm * WM + i * 16) * AL + kk], AL);
            if (NT) {
                wmma::fragment<wmma::matrix_b, 16, 16, 8, wmma::precision::tf32, wmma::col_major> bf[FN];
#pragma unroll
                for (int j = 0; j < FN; j++)
                    wmma::load_matrix_sync(bf[j], &Bcur[(wn * WN + j * 16) * AL + kk], AL);
#pragma unroll
                for (int i = 0; i < FM; i++)
#pragma unroll
                    for (int j = 0; j < FN; j++)
                        wmma::mma_sync(acc[i][j], af[i], bf[j], acc[i][j]);
            } else {
                wmma::fragment<wmma::matrix_b, 16, 16, 8, wmma::precision::tf32, wmma::row_major> bf[FN];
#pragma unroll
                for (int j = 0; j < FN; j++)
                    wmma::load_matrix_sync(bf[j], &Bcur[kk * BLnn + wn * WN + j * 16], BLnn);
#pragma unroll
                for (int i = 0; i < FM; i++)
#pragma unroll
                    for (int j = 0; j < FN; j++)
                        wmma::mma_sync(acc[i][j], af[i], bf[j], acc[i][j]);
            }
        }
    }

#pragma unroll
    for (int i = 0; i < FM; i++)
#pragma unroll
        for (int j = 0; j < FN; j++) {
            if (RELU) {
#pragma unroll
                for (int t = 0; t < acc[i][j].num_elements; t++)
                    acc[i][j].x[t] = fmaxf(acc[i][j].x[t], 0.f);
            }
            wmma::store_matrix_sync(C + (long long)(wm * WM + i * 16) * ldc + wn * WN + j * 16,
                                    acc[i][j], ldc, wmma::mem_row_major);
        }
}

// ---------------- shift + mask + softmax (in-place on g_attn) ----------------
__global__ void __launch_bounds__(256) softmax_kernel()
{
    int i = blockIdx.x, bh = blockIdx.y, tid = threadIdx.x;
    size_t base = ((size_t)bh * QLEN + i) * KLEN;
    const float* ac = g_attn + base;
    const float* bd = g_bd + base;
    float* p = g_attn + base;
    int vlen = i + MLEN + 1;
    int off  = QLEN - 1 - i;
    const float scale = 0.03125f;

    __shared__ float red[256];
    float mx = -1e30f;
    for (int j = tid; j < vlen; j += 256)
        mx = fmaxf(mx, (ac[j] + bd[j + off]) * scale);
    red[tid] = mx; __syncthreads();
    for (int s = 128; s; s >>= 1) { if (tid < s) red[tid] = fmaxf(red[tid], red[tid + s]); __syncthreads(); }
    float m = red[0]; __syncthreads();

    float sum = 0.f;
    for (int j = tid; j < vlen; j += 256) {
        float e = expf((ac[j] + bd[j + off]) * scale - m);
        p[j] = e;
        sum += e;
    }
    red[tid] = sum; __syncthreads();
    for (int s = 128; s; s >>= 1) { if (tid < s) red[tid] += red[tid + s]; __syncthreads(); }
    float inv = 1.f / red[0];

    for (int j = tid; j < KLEN; j += 256)
        p[j] = (j < vlen) ? p[j] * inv : 0.f;
}

// ---------------- fused add + LayerNorm ----------------
__global__ void __launch_bounds__(256) add_ln_kernel(
    const float* __restrict__ a, const float* __restrict__ b,
    const float* __restrict__ gamma, const float* __restrict__ beta,
    float* __restrict__ out)
{
    int row = blockIdx.x, tid = threadIdx.x;
    __shared__ float sh[E_];
    __shared__ float red[256];
    size_t base = (size_t)row * E_;

    float s = 0.f;
    for (int c = tid; c < E_; c += 256) { float v = a[base + c] + b[base + c]; sh[c] = v; s += v; }
    red[tid] = s; __syncthreads();
    for (int st = 128; st; st >>= 1) { if (tid < st) red[tid] += red[tid + st]; __syncthreads(); }
    float mu = red[0] * (1.f / E_); __syncthreads();

    float vs = 0.f;
    for (int c = tid; c < E_; c += 256) { float d = sh[c] - mu; vs += d * d; }
    red[tid] = vs; __syncthreads();
    for (int st = 128; st; st >>= 1) { if (tid < st) red[tid] += red[tid + st]; __syncthreads(); }
    float rstd = rsqrtf(red[0] * (1.f / E_) + 1e-3f);

    for (int c = tid; c < E_; c += 256)
        out[base + c] = (sh[c] - mu) * rstd * gamma[c] + beta[c];
}

// ---------------- host ----------------
#define GEMM_NN      gemm_db<128,128,32,64,32,0,0>
#define GEMM_NN_RELU gemm_db<128,128,32,64,32,0,1>
#define GEMM_NT      gemm_db<128,128,32,64,32,1,0>
#define GEMM_PV      gemm_db<128, 64,32,32,32,0,0>

static const int SZ_NN = 3 * (128*36 + 32*132) * 4;   // 105984
static const int SZ_NT = 3 * (128*36 + 128*36) * 4;   // 110592
static const int SZ_PV = 3 * (128*36 + 32*68) * 4;    // 81408

extern "C" void kernel_launch(void* const* d_in, const int* in_sizes, int n_in,
                              void* d_out, int out_size)
{
    const float* w      = (const float*)d_in[0];
    const float* r      = (const float*)d_in[1];
    const float* member = (const float*)d_in[2];
    const float* Wq  = (const float*)d_in[4];
    const float* Wk  = (const float*)d_in[5];
    const float* Wv  = (const float*)d_in[6];
    const float* Wr  = (const float*)d_in[7];
    const float* Wo  = (const float*)d_in[8];
    const float* rwb = (const float*)d_in[9];
    const float* rrb = (const float*)d_in[10];
    const float* ln1g = (const float*)d_in[11];
    const float* ln1b = (const float*)d_in[12];
    const float* W1  = (const float*)d_in[13];
    const float* W2  = (const float*)d_in[14];
    const float* ln2g = (const float*)d_in[15];
    const float* ln2b = (const float*)d_in[16];

    float *cat_, *q_, *qw_, *qr_, *k_, *v_, *rp_, *attn_, *bd_, *o_, *x_, *h1_, *y_;
    cudaGetSymbolAddress((void**)&cat_,  g_cat);
    cudaGetSymbolAddress((void**)&q_,    g_q);
    cudaGetSymbolAddress((void**)&qw_,   g_qw);
    cudaGetSymbolAddress((void**)&qr_,   g_qr);
    cudaGetSymbolAddress((void**)&k_,    g_k);
    cudaGetSymbolAddress((void**)&v_,    g_v);
    cudaGetSymbolAddress((void**)&rp_,   g_rp);
    cudaGetSymbolAddress((void**)&attn_, g_attn);
    cudaGetSymbolAddress((void**)&bd_,   g_bd);
    cudaGetSymbolAddress((void**)&o_,    g_o);
    cudaGetSymbolAddress((void**)&x_,    g_x);
    cudaGetSymbolAddress((void**)&h1_,   g_h1);
    cudaGetSymbolAddress((void**)&y_,    g_y);

    cudaFuncSetAttribute(GEMM_NN,      cudaFuncAttributeMaxDynamicSharedMemorySize, SZ_NN);
    cudaFuncSetAttribute(GEMM_NN_RELU, cudaFuncAttributeMaxDynamicSharedMemorySize, SZ_NN);
    cudaFuncSetAttribute(GEMM_NT,      cudaFuncAttributeMaxDynamicSharedMemorySize, SZ_NT);
    cudaFuncSetAttribute(GEMM_PV,      cudaFuncAttributeMaxDynamicSharedMemorySize, SZ_PV);

    // 1) cat = concat(member, w)
    concat_kernel<<<4096, 256>>>((const float4*)member, (const float4*)w, (float4*)cat_);

    // 2) projections
    GEMM_NN<<<dim3(8, 16, 1), 256, SZ_NN>>>(w,    Wq, q_,  2048, 1024, 1024, 1024, 1024, 1024, 0,0,0,0,0,0, 1);
    GEMM_NN<<<dim3(8, 32, 1), 256, SZ_NN>>>(cat_, Wk, k_,  4096, 1024, 1024, 1024, 1024, 1024, 0,0,0,0,0,0, 1);
    GEMM_NN<<<dim3(8, 32, 1), 256, SZ_NN>>>(cat_, Wv, v_,  4096, 1024, 1024, 1024, 1024, 1024, 0,0,0,0,0,0, 1);
    GEMM_NN<<<dim3(8, 16, 1), 256, SZ_NN>>>(r,    Wr, rp_, 2048, 1024, 1024, 1024, 1024, 1024, 0,0,0,0,0,0, 1);

    // 3) biased q copies (one pass)
    bias_add2_kernel<<<8192, 256>>>(q_, rwb, rrb, qw_, qr_, 2097152);

    // 4) AC[b,h] = qw @ k^T   (batched over 32 bh)
    GEMM_NT<<<dim3(16, 8, 32), 256, SZ_NT>>>(qw_, k_, attn_,
        1024, 2048, 64, 1024, 1024, 2048,
        1048576LL, 64LL, 2097152LL, 64LL, 33554432LL, 2097152LL, 16);

    // 5) BD_raw[b,h] = qr @ rp^T  (rp shared over batch)
    GEMM_NT<<<dim3(16, 8, 32), 256, SZ_NT>>>(qr_, rp_, bd_,
        1024, 2048, 64, 1024, 1024, 2048,
        1048576LL, 64LL, 0LL, 64LL, 33554432LL, 2097152LL, 16);

    // 6) rel_shift + mask + softmax (in-place)
    softmax_kernel<<<dim3(QLEN, B_ * H_), 256>>>();

    // 7) O = P @ v
    GEMM_PV<<<dim3(1, 8, 32), 256, SZ_PV>>>(attn_, v_, o_,
        1024, 64, 2048, 2048, 1024, 1024,
        33554432LL, 2097152LL, 2097152LL, 64LL, 1048576LL, 64LL, 16);

    // 8) o @ Wo
    GEMM_NN<<<dim3(8, 16, 1), 256, SZ_NN>>>(o_, Wo, y_, 2048, 1024, 1024, 1024, 1024, 1024, 0,0,0,0,0,0, 1);

    // 9) x = LN(w + o@Wo)
    add_ln_kernel<<<2048, 256>>>(w, y_, ln1g, ln1b, x_);

    // 10) h1 = relu(x @ W1)
    GEMM_NN_RELU<<<dim3(32, 16, 1), 256, SZ_NN>>>(x_, W1, h1_, 2048, 4096, 1024, 1024, 4096, 4096, 0,0,0,0,0,0, 1);

    // 11) y = h1 @ W2
    GEMM_NN<<<dim3(8, 16, 1), 256, SZ_NN>>>(h1_, W2, y_, 2048, 1024, 4096, 4096, 1024, 1024, 0,0,0,0,0,0, 1);

    // 12) out = LN(y + x)
    add_ln_kernel<<<2048, 256>>>(y_, x_, ln2g, ln2b, (float*)d_out);
}

// round 5
// speedup vs baseline: 2.0192x; 1.1010x over previous
#include <cuda_runtime.h>
#include <mma.h>
#include <math.h>

using namespace nvcuda;

#define B_    2
#define QLEN  1024
#define MLEN  1024
#define KLEN  2048
#define E_    1024
#define H_    16
#define DH_   64
#define HD_   1024
#define FF_   4096

// ---------------- scratch (device globals: allocation-free) ----------------
__device__ float g_cat [(size_t)B_*KLEN*E_];
__device__ float g_q   [(size_t)B_*QLEN*HD_];
__device__ float g_qw  [(size_t)B_*QLEN*HD_];
__device__ float g_qr  [(size_t)B_*QLEN*HD_];
__device__ float g_k   [(size_t)B_*KLEN*HD_];
__device__ float g_v   [(size_t)B_*KLEN*HD_];
__device__ float g_rp  [(size_t)KLEN*HD_];
__device__ float g_attn[(size_t)B_*H_*QLEN*KLEN];     // AC, then P in-place
__device__ float g_bd  [(size_t)B_*H_*QLEN*KLEN];     // BD_raw
__device__ float g_o   [(size_t)B_*QLEN*HD_];
__device__ float g_x   [(size_t)B_*QLEN*E_];
__device__ float g_h1  [(size_t)B_*QLEN*FF_];
__device__ float g_y   [(size_t)B_*QLEN*E_];

// ---------------- helpers ----------------
__device__ __forceinline__ void cpa16(float* dst, const float* src) {
    unsigned d = (unsigned)__cvta_generic_to_shared(dst);
    asm volatile("cp.async.cg.shared.global [%0], [%1], 16;\n" :: "r"(d), "l"(src));
}
__device__ __forceinline__ void cpa_commit() { asm volatile("cp.async.commit_group;\n"); }

// ---------------- small elementwise kernels ----------------
__global__ void concat_kernel(const float4* __restrict__ member,
                              const float4* __restrict__ w,
                              float4* __restrict__ cat)
{
    int idx = blockIdx.x * 256 + threadIdx.x;
    const int per_b = (KLEN * E_) / 4;
    const int half  = (MLEN * E_) / 4;
    int b = idx / per_b;
    int r = idx - b * per_b;
    cat[idx] = (r < half) ? member[b * half + r] : w[b * half + (r - half)];
}

__global__ void bias_add2_kernel(const float* __restrict__ q,
                                 const float* __restrict__ b1,
                                 const float* __restrict__ b2,
                                 float* __restrict__ o1,
                                 float* __restrict__ o2, int n)
{
    int i = blockIdx.x * 256 + threadIdx.x;
    if (i < n) {
        float v = q[i];
        int c = i & (HD_ - 1);
        o1[i] = v + b1[c];
        o2[i] = v + b2[c];
    }
}

// ---------------- multi-stage cp.async tf32 WMMA GEMM, 64x64 warp tile ----------------
// NT=0: C = A @ B (B row-major [K,N]); NT=1: C = A @ B^T (B row-major [N,K])
template<int BM, int BN, int BK, int WM, int WN, int NWARP, int NSTG, int NT, int RELU>
__global__ void __launch_bounds__(NWARP*32, 2) gemm4(
    const float* __restrict__ Ag, const float* __restrict__ Bg, float* __restrict__ Cg,
    int K, int lda, int ldb, int ldc,
    long long sAb, long long sAh, long long sBb, long long sBh,
    long long sCb, long long sCh, int Hn)
{
    constexpr int NTH  = NWARP * 32;
    constexpr int AL   = BK + 4;            // padded lead for A (and NT B)
    constexpr int BLnn = BN + 4;            // padded lead for NN B
    constexpr int ASZ  = BM * AL;
    constexpr int BSZ  = NT ? BN * AL : BK * BLnn;
    constexpr int STG  = ASZ + BSZ;
    constexpr int FM   = WM / 16;
    constexpr int FN   = WN / 16;
    constexpr int WROWS = BM / WM;

    extern __shared__ float sm[];

    int z = blockIdx.z, bb = z / Hn, hh = z - bb * Hn;
    const float* A  = Ag + (long long)bb * sAb + (long long)hh * sAh
                         + (long long)(blockIdx.y * BM) * lda;
    const float* Bp = Bg + (long long)bb * sBb + (long long)hh * sBh
                         + (NT ? (long long)(blockIdx.x * BN) * ldb
                               : (long long)(blockIdx.x * BN));
    float*       C  = Cg + (long long)bb * sCb + (long long)hh * sCh
                         + (long long)(blockIdx.y * BM) * ldc + blockIdx.x * BN;

    int tid = threadIdx.x;
    int wid = tid >> 5;
    int wm = wid % WROWS, wn = wid / WROWS;

    wmma::fragment<wmma::accumulator, 16, 16, 8, float> acc[FM][FN];
#pragma unroll
    for (int i = 0; i < FM; i++)
#pragma unroll
        for (int j = 0; j < FN; j++) wmma::fill_fragment(acc[i][j], 0.f);

    auto load_tile = [&](int s, int k0) {
        float* Ab = sm + s * STG;
        float* Bb = Ab + ASZ;
#pragma unroll
        for (int c = tid; c < BM * BK / 4; c += NTH) {
            int row = c / (BK / 4), c4 = c % (BK / 4);
            cpa16(&Ab[row * AL + c4 * 4], A + (long long)row * lda + k0 + c4 * 4);
        }
        if (NT) {
#pragma unroll
            for (int c = tid; c < BN * BK / 4; c += NTH) {
                int row = c / (BK / 4), c4 = c % (BK / 4);
                cpa16(&Bb[row * AL + c4 * 4], Bp + (long long)row * ldb + k0 + c4 * 4);
            }
        } else {
#pragma unroll
            for (int c = tid; c < BK * BN / 4; c += NTH) {
                int row = c / (BN / 4), c4 = c % (BN / 4);
                cpa16(&Bb[row * BLnn + c4 * 4], Bp + (long long)(k0 + row) * ldb + c4 * 4);
            }
        }
    };

    int niter = K / BK;
    int pre = (niter < NSTG - 1) ? niter : NSTG - 1;
    for (int s = 0; s < pre; ++s) { load_tile(s, s * BK); cpa_commit(); }

    for (int it = 0; it < niter; ++it) {
        asm volatile("cp.async.wait_group %0;\n" :: "n"(NSTG - 2));
        __syncthreads();
        int nx = it + NSTG - 1;
        if (nx < niter) load_tile(nx % NSTG, nx * BK);
        cpa_commit();   // uniform commit (empty groups at tail keep wait math exact)

        float* Acur = sm + (it % NSTG) * STG;
        float* Bcur = Acur + ASZ;

#pragma unroll
        for (int kk = 0; kk < BK; kk += 8) {
            wmma::fragment<wmma::matrix_a, 16, 16, 8, wmma::precision::tf32, wmma::row_major> af[FM];
#pragma unroll
            for (int i = 0; i < FM; i++)
                wmma::load_matrix_sync(af[i], &Acur[(wm * WM + i * 16) * AL + kk], AL);
            if (NT) {
                wmma::fragment<wmma::matrix_b, 16, 16, 8, wmma::precision::tf32, wmma::col_major> bf[FN];
#pragma unroll
                for (int j = 0; j < FN; j++)
                    wmma::load_matrix_sync(bf[j], &Bcur[(wn * WN + j * 16) * AL + kk], AL);
#pragma unroll
                for (int i = 0; i < FM; i++)
#pragma unroll
                    for (int j = 0; j < FN; j++)
                        wmma::mma_sync(acc[i][j], af[i], bf[j], acc[i][j]);
            } else {
                wmma::fragment<wmma::matrix_b, 16, 16, 8, wmma::precision::tf32, wmma::row_major> bf[FN];
#pragma unroll
                for (int j = 0; j < FN; j++)
                    wmma::load_matrix_sync(bf[j], &Bcur[kk * BLnn + wn * WN + j * 16], BLnn);
#pragma unroll
                for (int i = 0; i < FM; i++)
#pragma unroll
                    for (int j = 0; j < FN; j++)
                        wmma::mma_sync(acc[i][j], af[i], bf[j], acc[i][j]);
            }
        }
    }

#pragma unroll
    for (int i = 0; i < FM; i++)
#pragma unroll
        for (int j = 0; j < FN; j++) {
            if (RELU) {
#pragma unroll
                for (int t = 0; t < acc[i][j].num_elements; t++)
                    acc[i][j].x[t] = fmaxf(acc[i][j].x[t], 0.f);
            }
            wmma::store_matrix_sync(C + (long long)(wm * WM + i * 16) * ldc + wn * WN + j * 16,
                                    acc[i][j], ldc, wmma::mem_row_major);
        }
}

// ---------------- shift + mask + softmax (in-place on g_attn) ----------------
__global__ void __launch_bounds__(256) softmax_kernel()
{
    int i = blockIdx.x, bh = blockIdx.y, tid = threadIdx.x;
    size_t base = ((size_t)bh * QLEN + i) * KLEN;
    const float* ac = g_attn + base;
    const float* bd = g_bd + base;
    float* p = g_attn + base;
    int vlen = i + MLEN + 1;
    int off  = QLEN - 1 - i;
    const float scale = 0.03125f;

    __shared__ float red[256];
    float mx = -1e30f;
    for (int j = tid; j < vlen; j += 256)
        mx = fmaxf(mx, (ac[j] + bd[j + off]) * scale);
    red[tid] = mx; __syncthreads();
    for (int s = 128; s; s >>= 1) { if (tid < s) red[tid] = fmaxf(red[tid], red[tid + s]); __syncthreads(); }
    float m = red[0]; __syncthreads();

    float sum = 0.f;
    for (int j = tid; j < vlen; j += 256) {
        float e = expf((ac[j] + bd[j + off]) * scale - m);
        p[j] = e;
        sum += e;
    }
    red[tid] = sum; __syncthreads();
    for (int s = 128; s; s >>= 1) { if (tid < s) red[tid] += red[tid + s]; __syncthreads(); }
    float inv = 1.f / red[0];

    for (int j = tid; j < KLEN; j += 256)
        p[j] = (j < vlen) ? p[j] * inv : 0.f;
}

// ---------------- fused add + LayerNorm ----------------
__global__ void __launch_bounds__(256) add_ln_kernel(
    const float* __restrict__ a, const float* __restrict__ b,
    const float* __restrict__ gamma, const float* __restrict__ beta,
    float* __restrict__ out)
{
    int row = blockIdx.x, tid = threadIdx.x;
    __shared__ float sh[E_];
    __shared__ float red[256];
    size_t base = (size_t)row * E_;

    float s = 0.f;
    for (int c = tid; c < E_; c += 256) { float v = a[base + c] + b[base + c]; sh[c] = v; s += v; }
    red[tid] = s; __syncthreads();
    for (int st = 128; st; st >>= 1) { if (tid < st) red[tid] += red[tid + st]; __syncthreads(); }
    float mu = red[0] * (1.f / E_); __syncthreads();

    float vs = 0.f;
    for (int c = tid; c < E_; c += 256) { float d = sh[c] - mu; vs += d * d; }
    red[tid] = vs; __syncthreads();
    for (int st = 128; st; st >>= 1) { if (tid < st) red[tid] += red[tid + st]; __syncthreads(); }
    float rstd = rsqrtf(red[0] * (1.f / E_) + 1e-3f);

    for (int c = tid; c < E_; c += 256)
        out[base + c] = (sh[c] - mu) * rstd * gamma[c] + beta[c];
}

// ---------------- host ----------------
#define GEMM_NN      gemm4<128,128,16,64,64,4,4,0,0>
#define GEMM_NN_RELU gemm4<128,128,16,64,64,4,4,0,1>
#define GEMM_NT      gemm4<128,128,16,64,64,4,4,1,0>
#define GEMM_PV      gemm4<128, 64,32,64,32,4,3,0,0>

static const int SZ_NN = 4 * (128*20 + 16*132) * 4;   // 74752
static const int SZ_NT = 4 * (128*20 + 128*20) * 4;   // 81920
static const int SZ_PV = 3 * (128*36 + 32*68) * 4;    // 81408

extern "C" void kernel_launch(void* const* d_in, const int* in_sizes, int n_in,
                              void* d_out, int out_size)
{
    const float* w      = (const float*)d_in[0];
    const float* r      = (const float*)d_in[1];
    const float* member = (const float*)d_in[2];
    const float* Wq  = (const float*)d_in[4];
    const float* Wk  = (const float*)d_in[5];
    const float* Wv  = (const float*)d_in[6];
    const float* Wr  = (const float*)d_in[7];
    const float* Wo  = (const float*)d_in[8];
    const float* rwb = (const float*)d_in[9];
    const float* rrb = (const float*)d_in[10];
    const float* ln1g = (const float*)d_in[11];
    const float* ln1b = (const float*)d_in[12];
    const float* W1  = (const float*)d_in[13];
    const float* W2  = (const float*)d_in[14];
    const float* ln2g = (const float*)d_in[15];
    const float* ln2b = (const float*)d_in[16];

    float *cat_, *q_, *qw_, *qr_, *k_, *v_, *rp_, *attn_, *bd_, *o_, *x_, *h1_, *y_;
    cudaGetSymbolAddress((void**)&cat_,  g_cat);
    cudaGetSymbolAddress((void**)&q_,    g_q);
    cudaGetSymbolAddress((void**)&qw_,   g_qw);
    cudaGetSymbolAddress((void**)&qr_,   g_qr);
    cudaGetSymbolAddress((void**)&k_,    g_k);
    cudaGetSymbolAddress((void**)&v_,    g_v);
    cudaGetSymbolAddress((void**)&rp_,   g_rp);
    cudaGetSymbolAddress((void**)&attn_, g_attn);
    cudaGetSymbolAddress((void**)&bd_,   g_bd);
    cudaGetSymbolAddress((void**)&o_,    g_o);
    cudaGetSymbolAddress((void**)&x_,    g_x);
    cudaGetSymbolAddress((void**)&h1_,   g_h1);
    cudaGetSymbolAddress((void**)&y_,    g_y);

    cudaFuncSetAttribute(GEMM_NN,      cudaFuncAttributeMaxDynamicSharedMemorySize, SZ_NN);
    cudaFuncSetAttribute(GEMM_NN_RELU, cudaFuncAttributeMaxDynamicSharedMemorySize, SZ_NN);
    cudaFuncSetAttribute(GEMM_NT,      cudaFuncAttributeMaxDynamicSharedMemorySize, SZ_NT);
    cudaFuncSetAttribute(GEMM_PV,      cudaFuncAttributeMaxDynamicSharedMemorySize, SZ_PV);

    // 1) cat = concat(member, w)
    concat_kernel<<<4096, 256>>>((const float4*)member, (const float4*)w, (float4*)cat_);

    // 2) projections
    GEMM_NN<<<dim3(8, 16, 1), 128, SZ_NN>>>(w,    Wq, q_,  1024, 1024, 1024, 1024, 0,0,0,0,0,0, 1);
    GEMM_NN<<<dim3(8, 32, 1), 128, SZ_NN>>>(cat_, Wk, k_,  1024, 1024, 1024, 1024, 0,0,0,0,0,0, 1);
    GEMM_NN<<<dim3(8, 32, 1), 128, SZ_NN>>>(cat_, Wv, v_,  1024, 1024, 1024, 1024, 0,0,0,0,0,0, 1);
    GEMM_NN<<<dim3(8, 16, 1), 128, SZ_NN>>>(r,    Wr, rp_, 1024, 1024, 1024, 1024, 0,0,0,0,0,0, 1);

    // 3) biased q copies (one pass)
    bias_add2_kernel<<<8192, 256>>>(q_, rwb, rrb, qw_, qr_, 2097152);

    // 4) AC[b,h] = qw @ k^T   (batched over 32 bh)
    GEMM_NT<<<dim3(16, 8, 32), 128, SZ_NT>>>(qw_, k_, attn_,
        64, 1024, 1024, 2048,
        1048576LL, 64LL, 2097152LL, 64LL, 33554432LL, 2097152LL, 16);

    // 5) BD_raw[b,h] = qr @ rp^T  (rp shared over batch)
    GEMM_NT<<<dim3(16, 8, 32), 128, SZ_NT>>>(qr_, rp_, bd_,
        64, 1024, 1024, 2048,
        1048576LL, 64LL, 0LL, 64LL, 33554432LL, 2097152LL, 16);

    // 6) rel_shift + mask + softmax (in-place)
    softmax_kernel<<<dim3(QLEN, B_ * H_), 256>>>();

    // 7) O = P @ v
    GEMM_PV<<<dim3(1, 8, 32), 128, SZ_PV>>>(attn_, v_, o_,
        2048, 2048, 1024, 1024,
        33554432LL, 2097152LL, 2097152LL, 64LL, 1048576LL, 64LL, 16);

    // 8) o @ Wo
    GEMM_NN<<<dim3(8, 16, 1), 128, SZ_NN>>>(o_, Wo, y_, 1024, 1024, 1024, 1024, 0,0,0,0,0,0, 1);

    // 9) x = LN(w + o@Wo)
    add_ln_kernel<<<2048, 256>>>(w, y_, ln1g, ln1b, x_);

    // 10) h1 = relu(x @ W1)
    GEMM_NN_RELU<<<dim3(32, 16, 1), 128, SZ_NN>>>(x_, W1, h1_, 1024, 1024, 4096, 4096, 0,0,0,0,0,0, 1);

    // 11) y = h1 @ W2
    GEMM_NN<<<dim3(8, 16, 1), 128, SZ_NN>>>(h1_, W2, y_, 4096, 4096, 1024, 1024, 0,0,0,0,0,0, 1);

    // 12) out = LN(y + x)
    add_ln_kernel<<<2048, 256>>>(y_, x_, ln2g, ln2b, (float*)d_out);
}

// round 7
// speedup vs baseline: 2.1951x; 1.0871x over previous
#include <cuda_runtime.h>
#include <mma.h>
#include <math.h>

using namespace nvcuda;

#define B_    2
#define QLEN  1024
#define MLEN  1024
#define KLEN  2048
#define E_    1024
#define H_    16
#define DH_   64
#define HD_   1024
#define FF_   4096

// ---------------- scratch (device globals: allocation-free) ----------------
__device__ float g_cat [(size_t)B_*KLEN*E_];
__device__ float g_q   [(size_t)B_*QLEN*HD_];
__device__ float g_qw  [(size_t)B_*QLEN*HD_];
__device__ float g_qr  [(size_t)B_*QLEN*HD_];
__device__ float g_k   [(size_t)B_*KLEN*HD_];
__device__ float g_v   [(size_t)B_*KLEN*HD_];
__device__ float g_rp  [(size_t)KLEN*HD_];
__device__ float g_attn[(size_t)B_*H_*QLEN*KLEN];     // AC, then P in-place
__device__ float g_bd  [(size_t)B_*H_*QLEN*KLEN];     // BD_raw
__device__ float g_pv  [(size_t)8*B_*QLEN*HD_];       // PV split-K partials (64MB)
__device__ float g_o   [(size_t)B_*QLEN*HD_];
__device__ float g_x   [(size_t)B_*QLEN*E_];
__device__ float g_h1  [(size_t)B_*QLEN*FF_];
__device__ float g_y   [(size_t)B_*QLEN*E_];
__device__ float g_y2  [(size_t)B_*QLEN*E_];

// ---------------- helpers ----------------
__device__ __forceinline__ void cpa16(float* dst, const float* src) {
    unsigned d = (unsigned)__cvta_generic_to_shared(dst);
    asm volatile("cp.async.cg.shared.global [%0], [%1], 16;\n" :: "r"(d), "l"(src));
}
__device__ __forceinline__ void cpa_commit() { asm volatile("cp.async.commit_group;\n"); }

// ---------------- small elementwise kernels ----------------
__global__ void concat_kernel(const float4* __restrict__ member,
                              const float4* __restrict__ w,
                              float4* __restrict__ cat)
{
    int idx = blockIdx.x * 256 + threadIdx.x;
    const int per_b = (KLEN * E_) / 4;
    const int half  = (MLEN * E_) / 4;
    int b = idx / per_b;
    int r = idx - b * per_b;
    cat[idx] = (r < half) ? member[b * half + r] : w[b * half + (r - half)];
}

__global__ void bias_add2_kernel(const float* __restrict__ q,
                                 const float* __restrict__ b1,
                                 const float* __restrict__ b2,
                                 float* __restrict__ o1,
                                 float* __restrict__ o2, int n)
{
    int i = blockIdx.x * 256 + threadIdx.x;
    if (i < n) {
        float v = q[i];
        int c = i & (HD_ - 1);
        o1[i] = v + b1[c];
        o2[i] = v + b2[c];
    }
}

__global__ void reduce8_kernel(const float4* __restrict__ pv, float4* __restrict__ o)
{
    int i = blockIdx.x * 256 + threadIdx.x;           // 524288 total
    const int S = (B_*QLEN*HD_) / 4;                  // 524288
    float4 a = pv[i];
#pragma unroll
    for (int s = 1; s < 8; s++) {
        float4 b = pv[s * S + i];
        a.x += b.x; a.y += b.y; a.z += b.z; a.w += b.w;
    }
    o[i] = a;
}

// ---------------- multi-stage cp.async tf32 WMMA GEMM (NN/NT), from R4 ----------------
template<int BM, int BN, int BK, int WM, int WN, int NWARP, int NSTG, int NT, int RELU>
__global__ void __launch_bounds__(NWARP*32, 2) gemm4(
    const float* __restrict__ Ag, const float* __restrict__ Bg, float* __restrict__ Cg,
    int K, int lda, int ldb, int ldc,
    long long sAb, long long sAh, long long sBb, long long sBh,
    long long sCb, long long sCh, int Hn)
{
    constexpr int NTH  = NWARP * 32;
    constexpr int AL   = BK + 4;
    constexpr int BLnn = BN + 4;
    constexpr int ASZ  = BM * AL;
    constexpr int BSZ  = NT ? BN * AL : BK * BLnn;
    constexpr int STG  = ASZ + BSZ;
    constexpr int FM   = WM / 16;
    constexpr int FN   = WN / 16;
    constexpr int WROWS = BM / WM;

    extern __shared__ float sm[];

    int z = blockIdx.z, bb = z / Hn, hh = z - bb * Hn;
    const float* A  = Ag + (long long)bb * sAb + (long long)hh * sAh
                         + (long long)(blockIdx.y * BM) * lda;
    const float* Bp = Bg + (long long)bb * sBb + (long long)hh * sBh
                         + (NT ? (long long)(blockIdx.x * BN) * ldb
                               : (long long)(blockIdx.x * BN));
    float*       C  = Cg + (long long)bb * sCb + (long long)hh * sCh
                         + (long long)(blockIdx.y * BM) * ldc + blockIdx.x * BN;

    int tid = threadIdx.x;
    int wid = tid >> 5;
    int wm = wid % WROWS, wn = wid / WROWS;

    wmma::fragment<wmma::accumulator, 16, 16, 8, float> acc[FM][FN];
#pragma unroll
    for (int i = 0; i < FM; i++)
#pragma unroll
        for (int j = 0; j < FN; j++) wmma::fill_fragment(acc[i][j], 0.f);

    auto load_tile = [&](int s, int k0) {
        float* Ab = sm + s * STG;
        float* Bb = Ab + ASZ;
#pragma unroll
        for (int c = tid; c < BM * BK / 4; c += NTH) {
            int row = c / (BK / 4), c4 = c % (BK / 4);
            cpa16(&Ab[row * AL + c4 * 4], A + (long long)row * lda + k0 + c4 * 4);
        }
        if (NT) {
#pragma unroll
            for (int c = tid; c < BN * BK / 4; c += NTH) {
                int row = c / (BK / 4), c4 = c % (BK / 4);
                cpa16(&Bb[row * AL + c4 * 4], Bp + (long long)row * ldb + k0 + c4 * 4);
            }
        } else {
#pragma unroll
            for (int c = tid; c < BK * BN / 4; c += NTH) {
                int row = c / (BN / 4), c4 = c % (BN / 4);
                cpa16(&Bb[row * BLnn + c4 * 4], Bp + (long long)(k0 + row) * ldb + c4 * 4);
            }
        }
    };

    int niter = K / BK;
    int pre = (niter < NSTG - 1) ? niter : NSTG - 1;
    for (int s = 0; s < pre; ++s) { load_tile(s, s * BK); cpa_commit(); }

    for (int it = 0; it < niter; ++it) {
        asm volatile("cp.async.wait_group %0;\n" :: "n"(NSTG - 2));
        __syncthreads();
        int nx = it + NSTG - 1;
        if (nx < niter) load_tile(nx % NSTG, nx * BK);
        cpa_commit();

        float* Acur = sm + (it % NSTG) * STG;
        float* Bcur = Acur + ASZ;

#pragma unroll
        for (int kk = 0; kk < BK; kk += 8) {
            wmma::fragment<wmma::matrix_a, 16, 16, 8, wmma::precision::tf32, wmma::row_major> af[FM];
#pragma unroll
            for (int i = 0; i < FM; i++)
                wmma::load_matrix_sync(af[i], &Acur[(wm * WM + i * 16) * AL + kk], AL);
            if (NT) {
                wmma::fragment<wmma::matrix_b, 16, 16, 8, wmma::precision::tf32, wmma::col_major> bf[FN];
#pragma unroll
                for (int j = 0; j < FN; j++)
                    wmma::load_matrix_sync(bf[j], &Bcur[(wn * WN + j * 16) * AL + kk], AL);
#pragma unroll
                for (int i = 0; i < FM; i++)
#pragma unroll
                    for (int j = 0; j < FN; j++)
                        wmma::mma_sync(acc[i][j], af[i], bf[j], acc[i][j]);
            } else {
                wmma::fragment<wmma::matrix_b, 16, 16, 8, wmma::precision::tf32, wmma::row_major> bf[FN];
#pragma unroll
                for (int j = 0; j < FN; j++)
                    wmma::load_matrix_sync(bf[j], &Bcur[kk * BLnn + wn * WN + j * 16], BLnn);
#pragma unroll
                for (int i = 0; i < FM; i++)
#pragma unroll
                    for (int j = 0; j < FN; j++)
                        wmma::mma_sync(acc[i][j], af[i], bf[j], acc[i][j]);
            }
        }
    }

#pragma unroll
    for (int i = 0; i < FM; i++)
#pragma unroll
        for (int j = 0; j < FN; j++) {
            if (RELU) {
#pragma unroll
                for (int t = 0; t < acc[i][j].num_elements; t++)
                    acc[i][j].x[t] = fmaxf(acc[i][j].x[t], 0.f);
            }
            wmma::store_matrix_sync(C + (long long)(wm * WM + i * 16) * ldc + wn * WN + j * 16,
                                    acc[i][j], ldc, wmma::mem_row_major);
        }
}

// ---------------- NN GEMM with extra split/batch dimension in blockIdx.z ----------------
// z = ss*nbh + bh;  bh = bb*Hn + hh.  ss applies pointer-delta strides sAs/sBs/sCs.
template<int BM, int BN, int BK, int WM, int WN, int NWARP, int NSTG>
__global__ void __launch_bounds__(NWARP*32, 2) gemm_s(
    const float* __restrict__ Ag, const float* __restrict__ Bg, float* __restrict__ Cg,
    int K, int lda, int ldb, int ldc,
    long long sAb, long long sAh, long long sBb, long long sBh,
    long long sCb, long long sCh, int Hn, int nbh,
    long long sAs, long long sBs, long long sCs)
{
    constexpr int NTH  = NWARP * 32;
    constexpr int AL   = BK + 4;
    constexpr int BLnn = BN + 4;
    constexpr int ASZ  = BM * AL;
    constexpr int BSZ  = BK * BLnn;
    constexpr int STG  = ASZ + BSZ;
    constexpr int FM   = WM / 16;
    constexpr int FN   = WN / 16;
    constexpr int WROWS = BM / WM;

    extern __shared__ float sm[];

    int zz = blockIdx.z;
    int ss = zz / nbh, bh = zz - ss * nbh;
    int bb = bh / Hn, hh = bh - bb * Hn;
    const float* A  = Ag + (long long)ss * sAs + (long long)bb * sAb + (long long)hh * sAh
                         + (long long)(blockIdx.y * BM) * lda;
    const float* Bp = Bg + (long long)ss * sBs + (long long)bb * sBb + (long long)hh * sBh
                         + (long long)(blockIdx.x * BN);
    float*       C  = Cg + (long long)ss * sCs + (long long)bb * sCb + (long long)hh * sCh
                         + (long long)(blockIdx.y * BM) * ldc + blockIdx.x * BN;

    int tid = threadIdx.x;
    int wid = tid >> 5;
    int wm = wid % WROWS, wn = wid / WROWS;

    wmma::fragment<wmma::accumulator, 16, 16, 8, float> acc[FM][FN];
#pragma unroll
    for (int i = 0; i < FM; i++)
#pragma unroll
        for (int j = 0; j < FN; j++) wmma::fill_fragment(acc[i][j], 0.f);

    auto load_tile = [&](int s, int k0) {
        float* Ab = sm + s * STG;
        float* Bb = Ab + ASZ;
#pragma unroll
        for (int c = tid; c < BM * BK / 4; c += NTH) {
            int row = c / (BK / 4), c4 = c % (BK / 4);
            cpa16(&Ab[row * AL + c4 * 4], A + (long long)row * lda + k0 + c4 * 4);
        }
#pragma unroll
        for (int c = tid; c < BK * BN / 4; c += NTH) {
            int row = c / (BN / 4), c4 = c % (BN / 4);
            cpa16(&Bb[row * BLnn + c4 * 4], Bp + (long long)(k0 + row) * ldb + c4 * 4);
        }
    };

    int niter = K / BK;
    int pre = (niter < NSTG - 1) ? niter : NSTG - 1;
    for (int s = 0; s < pre; ++s) { load_tile(s, s * BK); cpa_commit(); }

    for (int it = 0; it < niter; ++it) {
        asm volatile("cp.async.wait_group %0;\n" :: "n"(NSTG - 2));
        __syncthreads();
        int nx = it + NSTG - 1;
        if (nx < niter) load_tile(nx % NSTG, nx * BK);
        cpa_commit();

        float* Acur = sm + (it % NSTG) * STG;
        float* Bcur = Acur + ASZ;

#pragma unroll
        for (int kk = 0; kk < BK; kk += 8) {
            wmma::fragment<wmma::matrix_a, 16, 16, 8, wmma::precision::tf32, wmma::row_major> af[FM];
#pragma unroll
            for (int i = 0; i < FM; i++)
                wmma::load_matrix_sync(af[i], &Acur[(wm * WM + i * 16) * AL + kk], AL);
            wmma::fragment<wmma::matrix_b, 16, 16, 8, wmma::precision::tf32, wmma::row_major> bf[FN];
#pragma unroll
            for (int j = 0; j < FN; j++)
                wmma::load_matrix_sync(bf[j], &Bcur[kk * BLnn + wn * WN + j * 16], BLnn);
#pragma unroll
            for (int i = 0; i < FM; i++)
#pragma unroll
                for (int j = 0; j < FN; j++)
                    wmma::mma_sync(acc[i][j], af[i], bf[j], acc[i][j]);
        }
    }

#pragma unroll
    for (int i = 0; i < FM; i++)
#pragma unroll
        for (int j = 0; j < FN; j++)
            wmma::store_matrix_sync(C + (long long)(wm * WM + i * 16) * ldc + wn * WN + j * 16,
                                    acc[i][j], ldc, wmma::mem_row_major);
}

// ---------------- shift + mask + softmax (in-place on g_attn) ----------------
__global__ void __launch_bounds__(256) softmax_kernel()
{
    int i = blockIdx.x, bh = blockIdx.y, tid = threadIdx.x;
    size_t base = ((size_t)bh * QLEN + i) * KLEN;
    const float* ac = g_attn + base;
    const float* bd = g_bd + base;
    float* p = g_attn + base;
    int vlen = i + MLEN + 1;
    int off  = QLEN - 1 - i;
    const float scale = 0.03125f;

    __shared__ float red[256];
    float mx = -1e30f;
    for (int j = tid; j < vlen; j += 256)
        mx = fmaxf(mx, (ac[j] + bd[j + off]) * scale);
    red[tid] = mx; __syncthreads();
    for (int s = 128; s; s >>= 1) { if (tid < s) red[tid] = fmaxf(red[tid], red[tid + s]); __syncthreads(); }
    float m = red[0]; __syncthreads();

    float sum = 0.f;
    for (int j = tid; j < vlen; j += 256) {
        float e = expf((ac[j] + bd[j + off]) * scale - m);
        p[j] = e;
        sum += e;
    }
    red[tid] = sum; __syncthreads();
    for (int s = 128; s; s >>= 1) { if (tid < s) red[tid] += red[tid + s]; __syncthreads(); }
    float inv = 1.f / red[0];

    for (int j = tid; j < KLEN; j += 256)
        p[j] = (j < vlen) ? p[j] * inv : 0.f;
}

// ---------------- fused 3-input add + LayerNorm ----------------
__global__ void __launch_bounds__(256) add_ln3_kernel(
    const float* __restrict__ a, const float* __restrict__ b, const float* __restrict__ c,
    const float* __restrict__ gamma, const float* __restrict__ beta,
    float* __restrict__ out)
{
    int row = blockIdx.x, tid = threadIdx.x;
    __shared__ float sh[E_];
    __shared__ float red[256];
    size_t base = (size_t)row * E_;

    float s = 0.f;
    for (int col = tid; col < E_; col += 256) {
        float v = a[base + col] + b[base + col] + c[base + col];
        sh[col] = v; s += v;
    }
    red[tid] = s; __syncthreads();
    for (int st = 128; st; st >>= 1) { if (tid < st) red[tid] += red[tid + st]; __syncthreads(); }
    float mu = red[0] * (1.f / E_); __syncthreads();

    float vs = 0.f;
    for (int col = tid; col < E_; col += 256) { float d = sh[col] - mu; vs += d * d; }
    red[tid] = vs; __syncthreads();
    for (int st = 128; st; st >>= 1) { if (tid < st) red[tid] += red[tid + st]; __syncthreads(); }
    float rstd = rsqrtf(red[0] * (1.f / E_) + 1e-3f);

    for (int col = tid; col < E_; col += 256)
        out[base + col] = (sh[col] - mu) * rstd * gamma[col] + beta[col];
}

// ---------------- host ----------------
#define GEMM_S       gemm_s<128,128,16,64,64,4,4>
#define GEMM_PVS     gemm_s<128, 64,32,64,32,4,2>
#define GEMM_NN_RELU gemm4<128,128,16,64,64,4,4,0,1>
#define GEMM_NT      gemm4<128,128,32,64,64,4,2,1,0>

static const int SZ_S   = 4 * (128*20 + 16*132) * 4;   // 74752
static const int SZ_PVS = 2 * (128*36 + 32*68) * 4;    // 54272
static const int SZ_NN  = 4 * (128*20 + 16*132) * 4;   // 74752
static const int SZ_NT  = 2 * (128*36 + 128*36) * 4;   // 73728

extern "C" void kernel_launch(void* const* d_in, const int* in_sizes, int n_in,
                              void* d_out, int out_size)
{
    const float* w      = (const float*)d_in[0];
    const float* r      = (const float*)d_in[1];
    const float* member = (const float*)d_in[2];
    const float* Wq  = (const float*)d_in[4];
    const float* Wk  = (const float*)d_in[5];
    const float* Wv  = (const float*)d_in[6];
    const float* Wr  = (const float*)d_in[7];
    const float* Wo  = (const float*)d_in[8];
    const float* rwb = (const float*)d_in[9];
    const float* rrb = (const float*)d_in[10];
    const float* ln1g = (const float*)d_in[11];
    const float* ln1b = (const float*)d_in[12];
    const float* W1  = (const float*)d_in[13];
    const float* W2  = (const float*)d_in[14];
    const float* ln2g = (const float*)d_in[15];
    const float* ln2b = (const float*)d_in[16];

    float *cat_, *q_, *qw_, *qr_, *k_, *v_, *rp_, *attn_, *bd_, *pv_, *o_, *x_, *h1_, *y_, *y2_;
    cudaGetSymbolAddress((void**)&cat_,  g_cat);
    cudaGetSymbolAddress((void**)&q_,    g_q);
    cudaGetSymbolAddress((void**)&qw_,   g_qw);
    cudaGetSymbolAddress((void**)&qr_,   g_qr);
    cudaGetSymbolAddress((void**)&k_,    g_k);
    cudaGetSymbolAddress((void**)&v_,    g_v);
    cudaGetSymbolAddress((void**)&rp_,   g_rp);
    cudaGetSymbolAddress((void**)&attn_, g_attn);
    cudaGetSymbolAddress((void**)&bd_,   g_bd);
    cudaGetSymbolAddress((void**)&pv_,   g_pv);
    cudaGetSymbolAddress((void**)&o_,    g_o);
    cudaGetSymbolAddress((void**)&x_,    g_x);
    cudaGetSymbolAddress((void**)&h1_,   g_h1);
    cudaGetSymbolAddress((void**)&y_,    g_y);
    cudaGetSymbolAddress((void**)&y2_,   g_y2);

    cudaFuncSetAttribute(GEMM_S,       cudaFuncAttributeMaxDynamicSharedMemorySize, SZ_S);
    cudaFuncSetAttribute(GEMM_PVS,     cudaFuncAttributeMaxDynamicSharedMemorySize, SZ_PVS);
    cudaFuncSetAttribute(GEMM_NN_RELU, cudaFuncAttributeMaxDynamicSharedMemorySize, SZ_NN);
    cudaFuncSetAttribute(GEMM_NT,      cudaFuncAttributeMaxDynamicSharedMemorySize, SZ_NT);

    // 1) cat = concat(member, w)
    concat_kernel<<<4096, 256>>>((const float4*)member, (const float4*)w, (float4*)cat_);

    // 2a) merged {q = w@Wq, rp = r@Wr}  (z: ss=0 -> q, ss=1 -> rp)
    GEMM_S<<<dim3(8, 16, 2), 128, SZ_S>>>(w, Wq, q_,
        1024, 1024, 1024, 1024,
        0,0,0,0,0,0, 1, 1,
        (long long)(r - w), (long long)(Wr - Wq), (long long)(rp_ - q_));

    // 2b) merged {k = cat@Wk, v = cat@Wv}
    GEMM_S<<<dim3(8, 32, 2), 128, SZ_S>>>(cat_, Wk, k_,
        1024, 1024, 1024, 1024,
        0,0,0,0,0,0, 1, 1,
        0LL, (long long)(Wv - Wk), (long long)(v_ - k_));

    // 3) biased q copies (one pass)
    bias_add2_kernel<<<8192, 256>>>(q_, rwb, rrb, qw_, qr_, 2097152);

    // 4) AC[b,h] = qw @ k^T   (batched over 32 bh)
    GEMM_NT<<<dim3(16, 8, 32), 128, SZ_NT>>>(qw_, k_, attn_,
        64, 1024, 1024, 2048,
        1048576LL, 64LL, 2097152LL, 64LL, 33554432LL, 2097152LL, 16);

    // 5) BD_raw[b,h] = qr @ rp^T  (rp shared over batch)
    GEMM_NT<<<dim3(16, 8, 32), 128, SZ_NT>>>(qr_, rp_, bd_,
        64, 1024, 1024, 2048,
        1048576LL, 64LL, 0LL, 64LL, 33554432LL, 2097152LL, 16);

    // 6) rel_shift + mask + softmax (in-place)
    softmax_kernel<<<dim3(QLEN, B_ * H_), 256>>>();

    // 7) O partials = P @ v, split-K = 8 (z = ss*32 + bh)
    GEMM_PVS<<<dim3(1, 8, 256), 128, SZ_PVS>>>(attn_, v_, pv_,
        256, 2048, 1024, 1024,
        33554432LL, 2097152LL, 2097152LL, 64LL, 1048576LL, 64LL, 16, 32,
        256LL, 256LL*1024LL, 2097152LL);

    // 7b) reduce partials -> o
    reduce8_kernel<<<2048, 256>>>((const float4*)pv_, (float4*)o_);

    // 8) o @ Wo, split-K = 2 -> y (ss=0), y2 (ss=1)
    GEMM_S<<<dim3(8, 16, 2), 128, SZ_S>>>(o_, Wo, y_,
        512, 1024, 1024, 1024,
        0,0,0,0,0,0, 1, 1,
        512LL, 512LL*1024LL, (long long)(y2_ - y_));

    // 9) x = LN(w + y + y2)
    add_ln3_kernel<<<2048, 256>>>(w, y_, y2_, ln1g, ln1b, x_);

    // 10) h1 = relu(x @ W1)
    GEMM_NN_RELU<<<dim3(32, 16, 1), 128, SZ_NN>>>(x_, W1, h1_, 1024, 1024, 4096, 4096, 0,0,0,0,0,0, 1);

    // 11) h1 @ W2, split-K = 2 -> y, y2
    GEMM_S<<<dim3(8, 16, 2), 128, SZ_S>>>(h1_, W2, y_,
        2048, 4096, 1024, 1024,
        0,0,0,0,0,0, 1, 1,
        2048LL, 2048LL*1024LL, (long long)(y2_ - y_));

    // 12) out = LN(x + y + y2)
    add_ln3_kernel<<<2048, 256>>>(x_, y_, y2_, ln2g, ln2b, (float*)d_out);
}